// round 2
// baseline (speedup 1.0000x reference)
#include <cuda_runtime.h>
#include <math.h>

#define BATCH 32
#define HDIM  64
#define WDIM  64
#define HW    4096
#define KPTS  17

// ---------------- scratch (device globals; no allocations allowed) ----------
__device__ float g_bufA[(size_t)32 * 256 * 4096];
__device__ float g_bufB[(size_t)32 * 256 * 4096];
__device__ float g_cg[BATCH * KPTS * 2];

// ---------------- conv3x3 (SAME) + BN + ReLU --------------------------------
// Block tile: 64 cout x (4 rows x 64 cols). 8 cin per chunk.
// Per thread: 8 cout x 8 cols of one row -> 64 accumulators.
__global__ __launch_bounds__(256, 2)
void conv3x3_bn_relu(const float* __restrict__ in, const float* __restrict__ w,
                     const float* __restrict__ gam, const float* __restrict__ bet,
                     float* __restrict__ out, int Cin, int Cout)
{
    __shared__ float s_in[8][6][67];   // [cin][row -1..4][col -1..64], pad 67
    __shared__ float s_w[8][9][65];    // [cin][tap][cout], pad 65

    const int tid      = threadIdx.x;
    const int rowBase  = blockIdx.x * 4;
    const int coutBase = blockIdx.y * 64;
    const int b        = blockIdx.z;

    const int g   = tid & 31;         // 32 pixel-groups
    const int rt  = g >> 3;           // row in 4-row tile
    const int c0  = (g & 7) * 8;      // col base (8 cols per thread)
    const int oc0 = (tid >> 5) * 8;   // cout base (8 couts per thread)

    float acc[8][8];
#pragma unroll
    for (int i = 0; i < 8; i++)
#pragma unroll
        for (int j = 0; j < 8; j++) acc[i][j] = 0.f;

    const float* inB = in + (size_t)b * Cin * HW;

    for (int cb = 0; cb < Cin; cb += 8) {
        __syncthreads();
        // load input chunk: 8 cin x 6 rows x 66 cols (zero-padded border)
        for (int idx = tid; idx < 8 * 6 * 66; idx += 256) {
            int cin = idx / 396;
            int rem = idx - cin * 396;
            int r   = rem / 66;
            int c   = rem - r * 66;
            int gy  = rowBase + r - 1;
            int gx  = c - 1;
            float v = 0.f;
            if ((unsigned)gy < 64u && (unsigned)gx < 64u)
                v = inB[(size_t)(cb + cin) * HW + gy * 64 + gx];
            s_in[cin][r][c] = v;
        }
        // load weight chunk: 64 cout x 8 cin x 9 taps
        for (int idx = tid; idx < 64 * 72; idx += 256) {
            int co  = idx / 72;
            int r   = idx - co * 72;
            int cin = r / 9;
            int tap = r - cin * 9;
            s_w[cin][tap][co] =
                w[((size_t)(coutBase + co) * Cin + (cb + cin)) * 9 + tap];
        }
        __syncthreads();

#pragma unroll 1
        for (int cin = 0; cin < 8; ++cin) {
#pragma unroll
            for (int dy = 0; dy < 3; ++dy) {
                float iv[10];
#pragma unroll
                for (int t = 0; t < 10; t++) iv[t] = s_in[cin][rt + dy][c0 + t];
#pragma unroll
                for (int dx = 0; dx < 3; ++dx) {
                    float wv[8];
#pragma unroll
                    for (int i = 0; i < 8; i++) wv[i] = s_w[cin][dy * 3 + dx][oc0 + i];
#pragma unroll
                    for (int i = 0; i < 8; i++)
#pragma unroll
                        for (int j = 0; j < 8; j++)
                            acc[i][j] = fmaf(wv[i], iv[j + dx], acc[i][j]);
                }
            }
        }
    }

    // epilogue: BN (var=1.0 + eps) + ReLU
    const float inv = rsqrtf(1.0f + 1e-5f);
#pragma unroll
    for (int i = 0; i < 8; i++) {
        int co   = coutBase + oc0 + i;
        float sc = gam[co] * inv;
        float bi = bet[co];
        float* op = out + ((size_t)b * Cout + co) * HW + (rowBase + rt) * 64 + c0;
#pragma unroll
        for (int j = 0; j < 8; j++) {
            float v = fmaf(acc[i][j], sc, bi);
            op[j] = v > 0.f ? v : 0.f;
        }
    }
}

// ---------------- conv1x1 + bias (+ optional softplus) ----------------------
// MODE 0: out = conv + bias.  MODE 1: out = softplus(conv + bias).
template <int CIN, int COUT, int MODE>
__global__ __launch_bounds__(256)
void conv1x1_epi(const float* __restrict__ in, const float* __restrict__ w,
                 const float* __restrict__ bias, float* __restrict__ out)
{
    __shared__ float s_w[COUT * CIN];
    const int tid = threadIdx.x;
    for (int i = tid; i < COUT * CIN; i += 256) s_w[i] = w[i];
    __syncthreads();

    const int p = blockIdx.x * 256 + tid;   // pixel in image
    const int b = blockIdx.y;

    float acc[COUT];
#pragma unroll
    for (int k = 0; k < COUT; k++) acc[k] = 0.f;

    const float* ip = in + (size_t)b * CIN * HW + p;
#pragma unroll 4
    for (int c = 0; c < CIN; c++) {
        float v = ip[(size_t)c * HW];
#pragma unroll
        for (int k = 0; k < COUT; k++) acc[k] = fmaf(v, s_w[k * CIN + c], acc[k]);
    }

#pragma unroll
    for (int k = 0; k < COUT; k++) {
        float v = acc[k] + bias[k];
        if (MODE == 1) v = fmaxf(v, 0.f) + log1pf(expf(-fabsf(v)));
        out[((size_t)b * COUT + k) * HW + p] = v;
    }
}

// ---------------- soft-argmax over 64x64 heatmap per (b,k) ------------------
__global__ void soft_argmax_kernel(const float* __restrict__ heat,
                                   float* __restrict__ cg,
                                   float* __restrict__ scores)
{
    const int bk  = blockIdx.x;
    const int tid = threadIdx.x;
    const float* h = heat + (size_t)bk * HW;

    __shared__ float rs0[256], rs1[256], rs2[256];

    float m = -INFINITY;
    for (int p = tid; p < HW; p += 256) m = fmaxf(m, h[p]);
    rs0[tid] = m;
    __syncthreads();
    for (int s = 128; s > 0; s >>= 1) {
        if (tid < s) rs0[tid] = fmaxf(rs0[tid], rs0[tid + s]);
        __syncthreads();
    }
    const float mx = rs0[0];
    __syncthreads();

    float se = 0.f, sx = 0.f, sy = 0.f;
    for (int p = tid; p < HW; p += 256) {
        float e = expf(h[p] - mx);
        se += e;
        sx += e * (float)(p & 63);
        sy += e * (float)(p >> 6);
    }
    rs0[tid] = se; rs1[tid] = sx; rs2[tid] = sy;
    __syncthreads();
    for (int s = 128; s > 0; s >>= 1) {
        if (tid < s) {
            rs0[tid] += rs0[tid + s];
            rs1[tid] += rs1[tid + s];
            rs2[tid] += rs2[tid + s];
        }
        __syncthreads();
    }
    if (tid == 0) {
        scores[bk]     = mx;
        cg[2 * bk]     = rs1[0] / rs0[0];
        cg[2 * bk + 1] = rs2[0] / rs0[0];
    }
}

// ---------------- local refine + combine + offset sampling ------------------
__global__ void finalize_kernel(const float* __restrict__ heat,
                                const float* __restrict__ off,
                                const float* __restrict__ cg,
                                const float* __restrict__ alpha_p,
                                const float* __restrict__ fusion_p,
                                float* __restrict__ coords,
                                float* __restrict__ fw_out)
{
    const int t = blockIdx.x * blockDim.x + threadIdx.x;
    const float fwv = 1.f / (1.f + expf(-fusion_p[0]));
    if (t == 0) fw_out[0] = fwv;
    if (t >= BATCH * KPTS) return;

    const float a   = 1.f / (1.f + expf(-alpha_p[0]));
    const float cgx = cg[2 * t];
    const float cgy = cg[2 * t + 1];
    const int px = (int)rintf(fminf(fmaxf(cgx, 0.f), 63.f));
    const int py = (int)rintf(fminf(fmaxf(cgy, 0.f), 63.f));

    const float* h = heat + (size_t)t * HW;

    float mx = -INFINITY;
    for (int i = 0; i < 5; i++) {
        int ys = py + i - 2; if ((unsigned)ys >= 64u) continue;
        for (int j = 0; j < 5; j++) {
            int xs = px + j - 2; if ((unsigned)xs >= 64u) continue;
            mx = fmaxf(mx, h[ys * 64 + xs]);
        }
    }
    float sw = 0.f, sxw = 0.f, syw = 0.f;
    for (int i = 0; i < 5; i++) {
        int ys = py + i - 2; if ((unsigned)ys >= 64u) continue;
        for (int j = 0; j < 5; j++) {
            int xs = px + j - 2; if ((unsigned)xs >= 64u) continue;
            float e = expf(h[ys * 64 + xs] - mx);
            sw  += e;
            sxw += e * (float)xs;
            syw += e * (float)ys;
        }
    }
    const float rx = sxw / sw;
    const float ry = syw / sw;

    float cx = a * cgx + (1.f - a) * rx;
    float cy = a * cgy + (1.f - a) * ry;

    // bilinear sample of the 2 offset channels at (cx, cy)
    const float ix = fminf(fmaxf(cx, 0.f), 63.f);
    const float iy = fminf(fmaxf(cy, 0.f), 63.f);
    const float x0 = floorf(ix), y0 = floorf(iy);
    const float wx = ix - x0,  wy = iy - y0;
    const int x0i = min(max((int)x0, 0), 63);
    const int x1i = min(x0i + 1, 63);
    const int y0i = min(max((int)y0, 0), 63);
    const int y1i = min(y0i + 1, 63);

    const float* o0 = off + (size_t)(t * 2) * HW;   // channel k*2+0
    const float* o1 = o0 + HW;                      // channel k*2+1

    float a00 = o0[y0i * 64 + x0i], a01 = o0[y0i * 64 + x1i];
    float a10 = o0[y1i * 64 + x0i], a11 = o0[y1i * 64 + x1i];
    float v0 = (1.f - wy) * ((1.f - wx) * a00 + wx * a01)
             +        wy  * ((1.f - wx) * a10 + wx * a11);

    a00 = o1[y0i * 64 + x0i]; a01 = o1[y0i * 64 + x1i];
    a10 = o1[y1i * 64 + x0i]; a11 = o1[y1i * 64 + x1i];
    float v1 = (1.f - wy) * ((1.f - wx) * a00 + wx * a01)
             +        wy  * ((1.f - wx) * a10 + wx * a11);

    coords[2 * t]     = cx + fwv * v0;
    coords[2 * t + 1] = cy + fwv * v1;
}

// ---------------- launch ----------------------------------------------------
extern "C" void kernel_launch(void* const* d_in, const int* in_sizes, int n_in,
                              void* d_out, int out_size)
{
    const float* x    = (const float*)d_in[0];
    const float* w_s1 = (const float*)d_in[1];
    const float* g_s1 = (const float*)d_in[2];
    const float* b_s1 = (const float*)d_in[3];
    const float* w_s2 = (const float*)d_in[4];
    const float* g_s2 = (const float*)d_in[5];
    const float* b_s2 = (const float*)d_in[6];
    const float* w_h1 = (const float*)d_in[7];
    const float* g_h1 = (const float*)d_in[8];
    const float* b_h1 = (const float*)d_in[9];
    const float* w_h2 = (const float*)d_in[10];
    const float* c_h2 = (const float*)d_in[11];
    const float* w_o1 = (const float*)d_in[12];
    const float* g_o1 = (const float*)d_in[13];
    const float* b_o1 = (const float*)d_in[14];
    const float* w_o2 = (const float*)d_in[15];
    const float* c_o2 = (const float*)d_in[16];
    const float* w_v1 = (const float*)d_in[17];
    const float* g_v1 = (const float*)d_in[18];
    const float* b_v1 = (const float*)d_in[19];
    const float* w_v2 = (const float*)d_in[20];
    const float* c_v2 = (const float*)d_in[21];
    const float* alpha  = (const float*)d_in[22];
    const float* fusion = (const float*)d_in[23];

    float *bufA, *bufB, *cg;
    cudaGetSymbolAddress((void**)&bufA, g_bufA);
    cudaGetSymbolAddress((void**)&bufB, g_bufB);
    cudaGetSymbolAddress((void**)&cg,   g_cg);

    float* out    = (float*)d_out;
    float* heat   = out;                 // 32*17*4096      = 2228224
    float* off    = out + 2228224;       // 32*34*4096      = 4456448
    float* var    = out + 6684672;       // 32*17*4096      = 2228224
    float* fw     = out + 8912896;       // 1
    float* coords = out + 8912897;       // 32*17*2         = 1088
    float* scores = out + 8913985;       // 32*17           = 544

    dim3 blk(256);
    dim3 g256(16, 4, 32);   // row tiles, cout tiles (256/64), batch
    dim3 g128(16, 2, 32);   // cout = 128
    dim3 g1x1(16, 32);      // 4096/256 pixel tiles, batch

    // stem
    conv3x3_bn_relu<<<g256, blk>>>(x,    w_s1, g_s1, b_s1, bufA, 256, 256);
    conv3x3_bn_relu<<<g256, blk>>>(bufA, w_s2, g_s2, b_s2, bufB, 256, 256);
    // heat branch
    conv3x3_bn_relu<<<g256, blk>>>(bufB, w_h1, g_h1, b_h1, bufA, 256, 256);
    conv1x1_epi<256, 17, 0><<<g1x1, blk>>>(bufA, w_h2, c_h2, heat);
    // offset branch
    conv3x3_bn_relu<<<g256, blk>>>(bufB, w_o1, g_o1, b_o1, bufA, 256, 256);
    conv1x1_epi<256, 34, 0><<<g1x1, blk>>>(bufA, w_o2, c_o2, off);
    // variance branch
    conv3x3_bn_relu<<<g128, blk>>>(bufB, w_v1, g_v1, b_v1, bufA, 256, 128);
    conv1x1_epi<128, 17, 1><<<g1x1, blk>>>(bufA, w_v2, c_v2, var);
    // coordinate tail
    soft_argmax_kernel<<<BATCH * KPTS, 256>>>(heat, cg, scores);
    finalize_kernel<<<5, 128>>>(heat, off, cg, alpha, fusion, coords, fw);
}